// round 2
// baseline (speedup 1.0000x reference)
#include <cuda_runtime.h>
#include <math.h>

#define V 720
#define U 736
#define NXY 512
#define NTAPS 368

#define DU_D   1.2858
#define DSO_D  595.0
#define DOD_D  490.6
#define DSD_D  (DSO_D + DOD_D)
#define SVOX_D 400.0
#define PI_D   3.14159265358979323846

// padded parity-packed arrays
#define PADE 380            // base for odd-sample array (even outputs), %4==0
#define PODD 383            // base for even-sample array; odd group uses base PODD+1 (%4==0)
#define WLEN 1124

// ---- device-global scratch ----
__device__ float4 g_trig[V];        // (cb*DSD/DU, sb*DSD/DU, cb, sb)
__device__ float2 g_Qp[V * U];      // (Q[u], Q[u+1]) pairs

// ---------------------------------------------------------------------------
// Kernel 1: cosine weight + Ram-Lak conv (parity-packed, register-tiled),
// one block (192 thr) per view. Also writes the per-view trig table.
// ---------------------------------------------------------------------------
__global__ __launch_bounds__(192) void filter_kernel(const float* __restrict__ sino) {
    __shared__ __align__(16) float wo_s[WLEN];   // odd-j samples
    __shared__ __align__(16) float we_s[WLEN];   // even-j samples
    __shared__ __align__(16) float ho_s[NTAPS];  // tap coeffs (odd n)
    __shared__ float qrow[U];

    const int v = blockIdx.x;
    const int tid = threadIdx.x;

    for (int i = tid; i < WLEN; i += 192) { wo_s[i] = 0.0f; we_s[i] = 0.0f; }
    for (int k = tid; k < NTAPS; k += 192) {
        float d = (float)(PI_D * DU_D) * (float)(2 * k + 1);
        ho_s[k] = -1.0f / (d * d);
    }
    if (tid == 0) {
        float bf = (float)(2.0 * PI_D * (double)v / (double)V);
        float cb = (float)cos((double)bf);
        float sb = (float)sin((double)bf);
        float kk = (float)(DSD_D / DU_D);
        g_trig[v] = make_float4(cb * kk, sb * kk, cb, sb);
    }
    __syncthreads();

    // cosine weighting + parity scatter
    {
        const float* row = sino + v * U;
        const float dsd  = (float)DSD_D;
        const float dsd2 = (float)(DSD_D * DSD_D);
        const float du   = (float)DU_D;
        for (int u = tid; u < U; u += 192) {
            float us = ((float)u - 367.5f) * du;
            float w = row[u] * (dsd * rsqrtf(dsd2 + us * us));
            if (u & 1) wo_s[PADE + (u >> 1)] = w;
            else       we_s[PODD + (u >> 1)] = w;
        }
    }
    __syncthreads();

    // convolution: warps 0-2 -> even outputs, warps 3-5 -> odd outputs
    const int grp = tid / 96;
    const int t   = tid % 96;
    if (t < 92) {
        const int b = 4 * t;
        const float* A = grp ? (we_s + PODD + 1) : (wo_s + PADE);  // conv inputs
        const float* C = grp ? (wo_s + PADE)     : (we_s + PODD);  // center samples
        const float h0 = (float)(1.0 / (4.0 * DU_D * DU_D));

        float acc0 = h0 * C[b + 0];
        float acc1 = h0 * C[b + 1];
        float acc2 = h0 * C[b + 2];
        float acc3 = h0 * C[b + 3];

        // left window covers [b-4j-4, b-4j+3], right window [b+4j, b+4j+7]
        float4 Llo = *(const float4*)(A + b - 4);
        float4 Lhi = *(const float4*)(A + b);
        float4 rlo = *(const float4*)(A + b);
        float4 rhi = *(const float4*)(A + b + 4);

        #pragma unroll 4
        for (int j = 0; j < 92; j++) {
            float4 h4 = *(const float4*)(ho_s + 4 * j);
            // kk=0: L=lwin[3..6], R=rwin[0..3]
            acc0 += h4.x * (Llo.w + rlo.x);
            acc1 += h4.x * (Lhi.x + rlo.y);
            acc2 += h4.x * (Lhi.y + rlo.z);
            acc3 += h4.x * (Lhi.z + rlo.w);
            // kk=1: L=lwin[2..5], R=rwin[1..4]
            acc0 += h4.y * (Llo.z + rlo.y);
            acc1 += h4.y * (Llo.w + rlo.z);
            acc2 += h4.y * (Lhi.x + rlo.w);
            acc3 += h4.y * (Lhi.y + rhi.x);
            // kk=2: L=lwin[1..4], R=rwin[2..5]
            acc0 += h4.z * (Llo.y + rlo.z);
            acc1 += h4.z * (Llo.z + rlo.w);
            acc2 += h4.z * (Llo.w + rhi.x);
            acc3 += h4.z * (Lhi.x + rhi.y);
            // kk=3: L=lwin[0..3], R=rwin[3..6]
            acc0 += h4.w * (Llo.x + rlo.w);
            acc1 += h4.w * (Llo.y + rhi.x);
            acc2 += h4.w * (Llo.z + rhi.y);
            acc3 += h4.w * (Llo.w + rhi.z);
            // slide windows
            Lhi = Llo;
            Llo = *(const float4*)(A + b - 4 * j - 8);
            rlo = rhi;
            rhi = *(const float4*)(A + b + 4 * j + 8);
        }

        const float du = (float)DU_D;
        const int u0 = 8 * t + grp;
        qrow[u0 + 0] = du * acc0;
        qrow[u0 + 2] = du * acc1;
        qrow[u0 + 4] = du * acc2;
        qrow[u0 + 6] = du * acc3;
    }
    __syncthreads();

    // write overlapping pairs (Q[u], Q[u+1]) for single-LDG.64 lerp in BP
    for (int u = tid; u < U; u += 192) {
        float a = qrow[u];
        float bq = (u < U - 1) ? qrow[u + 1] : 0.0f;
        g_Qp[v * U + u] = make_float2(a, bq);
    }
}

// ---------------------------------------------------------------------------
// Kernel 2: weighted fan-beam backprojection.
// Block (32,4): threadIdx.x -> iy, each thread handles 4 ix (stride 4).
// Tile 32(y) x 16(x); grid (16, 32) = 512 blocks.
// ---------------------------------------------------------------------------
__global__ __launch_bounds__(128) void bp_kernel(float* __restrict__ out) {
    __shared__ __align__(16) float4 strig[V];

    const int tid = threadIdx.y * 32 + threadIdx.x;
    {
        const float* src = (const float*)g_trig;
        float* dst = (float*)strig;
        for (int i = tid; i < 4 * V; i += 128) dst[i] = src[i];
    }
    __syncthreads();

    const int iy  = blockIdx.x * 32 + threadIdx.x;
    const int ix0 = blockIdx.y * 16 + threadIdx.y;       // ix = ix0 + 4*m

    const float dx   = (float)(SVOX_D / (double)NXY);
    const float x0   = ((float)ix0 - 255.5f) * dx;
    const float y    = ((float)iy  - 255.5f) * dx;
    const float stp  = 4.0f * dx;
    const float c0   = 367.5f;
    const float dso  = (float)DSO_D;
    const float uMax = (float)(U - 1);

    float acc0 = 0.0f, acc1 = 0.0f, acc2 = 0.0f, acc3 = 0.0f;

    #pragma unroll 2
    for (int v = 0; v < V; v++) {
        float4 tg = strig[v];
        float tK0 = x0 * tg.x + y * tg.y;                 // t * DSD/DU
        float dtK = stp * tg.x;
        float D0  = dso + x0 * tg.w - y * tg.z;           // DSO - s
        float dD  = stp * tg.w;
        const float2* qv = g_Qp + v * U;

        #pragma unroll
        for (int m = 0; m < 4; m++) {
            float tK = tK0 + (float)m * dtK;
            float D  = D0  + (float)m * dD;
            float r;
            asm("rcp.approx.f32 %0, %1;" : "=f"(r) : "f"(D));
            float idx = fmaf(tK, r, c0);
            int i0 = __float2int_rd(idx);
            i0 = max(0, min(U - 2, i0));
            float f = idx - (float)i0;
            float2 q = __ldg(qv + i0);
            float val = fmaf(f, q.y - q.x, q.x);
            bool ok = (idx >= 0.0f) && (idx <= uMax);
            float pv = ok ? val : 0.0f;
            float r2 = r * r;
            if (m == 0) acc0 = fmaf(pv, r2, acc0);
            if (m == 1) acc1 = fmaf(pv, r2, acc1);
            if (m == 2) acc2 = fmaf(pv, r2, acc2);
            if (m == 3) acc3 = fmaf(pv, r2, acc3);
        }
    }

    // fold dso^2 and 0.5*dbeta into one scale
    const float scale = (float)(0.5 * (2.0 * PI_D / (double)V) * DSO_D * DSO_D);
    out[(ix0 + 0)  * NXY + iy] = acc0 * scale;
    out[(ix0 + 4)  * NXY + iy] = acc1 * scale;
    out[(ix0 + 8)  * NXY + iy] = acc2 * scale;
    out[(ix0 + 12) * NXY + iy] = acc3 * scale;
}

// ---------------------------------------------------------------------------
extern "C" void kernel_launch(void* const* d_in, const int* in_sizes, int n_in,
                              void* d_out, int out_size) {
    (void)in_sizes; (void)n_in; (void)out_size;
    const float* sino = (const float*)d_in[0];
    float* out = (float*)d_out;

    filter_kernel<<<V, 192>>>(sino);
    dim3 bpBlock(32, 4);
    dim3 bpGrid(NXY / 32, NXY / 16);
    bp_kernel<<<bpGrid, bpBlock>>>(out);
}

// round 3
// speedup vs baseline: 1.7652x; 1.7652x over previous
#include <cuda_runtime.h>
#include <math.h>

#define V 720
#define U 736
#define NXY 512
#define NTAPS 368

#define DU_D   1.2858
#define DSO_D  595.0
#define DOD_D  490.6
#define DSD_D  (DSO_D + DOD_D)
#define SVOX_D 400.0
#define PI_D   3.14159265358979323846

// padded parity-packed arrays
#define PADE 380
#define PODD 383
#define WLEN 1124

// ---- device-global scratch ----
__device__ float4 g_trig[V];        // (cb*DSD/DU, sb*DSD/DU, cb, sb)
__device__ float2 g_Qp[V * U];      // (Q[u], Q[u+1]) pairs

// ---------------------------------------------------------------------------
// Kernel 1: cosine weight + Ram-Lak conv (parity-packed, register-tiled),
// one block (192 thr) per view. Also writes the per-view trig table.
// ---------------------------------------------------------------------------
__global__ __launch_bounds__(192) void filter_kernel(const float* __restrict__ sino) {
    __shared__ __align__(16) float wo_s[WLEN];
    __shared__ __align__(16) float we_s[WLEN];
    __shared__ __align__(16) float ho_s[NTAPS];
    __shared__ float qrow[U];

    const int v = blockIdx.x;
    const int tid = threadIdx.x;

    for (int i = tid; i < WLEN; i += 192) { wo_s[i] = 0.0f; we_s[i] = 0.0f; }
    for (int k = tid; k < NTAPS; k += 192) {
        float d = (float)(PI_D * DU_D) * (float)(2 * k + 1);
        ho_s[k] = -1.0f / (d * d);
    }
    if (tid == 0) {
        float bf = (float)(2.0 * PI_D * (double)v / (double)V);
        float cb = (float)cos((double)bf);
        float sb = (float)sin((double)bf);
        float kk = (float)(DSD_D / DU_D);
        g_trig[v] = make_float4(cb * kk, sb * kk, cb, sb);
    }
    __syncthreads();

    {
        const float* row = sino + v * U;
        const float dsd  = (float)DSD_D;
        const float dsd2 = (float)(DSD_D * DSD_D);
        const float du   = (float)DU_D;
        for (int u = tid; u < U; u += 192) {
            float us = ((float)u - 367.5f) * du;
            float w = row[u] * (dsd * rsqrtf(dsd2 + us * us));
            if (u & 1) wo_s[PADE + (u >> 1)] = w;
            else       we_s[PODD + (u >> 1)] = w;
        }
    }
    __syncthreads();

    const int grp = tid / 96;
    const int t   = tid % 96;
    if (t < 92) {
        const int b = 4 * t;
        const float* A = grp ? (we_s + PODD + 1) : (wo_s + PADE);
        const float* C = grp ? (wo_s + PADE)     : (we_s + PODD);
        const float h0 = (float)(1.0 / (4.0 * DU_D * DU_D));

        float acc0 = h0 * C[b + 0];
        float acc1 = h0 * C[b + 1];
        float acc2 = h0 * C[b + 2];
        float acc3 = h0 * C[b + 3];

        float4 Llo = *(const float4*)(A + b - 4);
        float4 Lhi = *(const float4*)(A + b);
        float4 rlo = *(const float4*)(A + b);
        float4 rhi = *(const float4*)(A + b + 4);

        #pragma unroll 4
        for (int j = 0; j < 92; j++) {
            float4 h4 = *(const float4*)(ho_s + 4 * j);
            acc0 += h4.x * (Llo.w + rlo.x);
            acc1 += h4.x * (Lhi.x + rlo.y);
            acc2 += h4.x * (Lhi.y + rlo.z);
            acc3 += h4.x * (Lhi.z + rlo.w);
            acc0 += h4.y * (Llo.z + rlo.y);
            acc1 += h4.y * (Llo.w + rlo.z);
            acc2 += h4.y * (Lhi.x + rlo.w);
            acc3 += h4.y * (Lhi.y + rhi.x);
            acc0 += h4.z * (Llo.y + rlo.z);
            acc1 += h4.z * (Llo.z + rlo.w);
            acc2 += h4.z * (Llo.w + rhi.x);
            acc3 += h4.z * (Lhi.x + rhi.y);
            acc0 += h4.w * (Llo.x + rlo.w);
            acc1 += h4.w * (Llo.y + rhi.x);
            acc2 += h4.w * (Llo.z + rhi.y);
            acc3 += h4.w * (Llo.w + rhi.z);
            Lhi = Llo;
            Llo = *(const float4*)(A + b - 4 * j - 8);
            rlo = rhi;
            rhi = *(const float4*)(A + b + 4 * j + 8);
        }

        const float du = (float)DU_D;
        const int u0 = 8 * t + grp;
        qrow[u0 + 0] = du * acc0;
        qrow[u0 + 2] = du * acc1;
        qrow[u0 + 4] = du * acc2;
        qrow[u0 + 6] = du * acc3;
    }
    __syncthreads();

    for (int u = tid; u < U; u += 192) {
        float a = qrow[u];
        float bq = (u < U - 1) ? qrow[u + 1] : 0.0f;
        g_Qp[v * U + u] = make_float2(a, bq);
    }
}

// ---------------------------------------------------------------------------
// Kernel 2: weighted fan-beam backprojection.
// Block (32,8): iy = bx*32+tx, pixels ix0 = by*16+ty and ix0+8.
// 2-view x 2-pixel manual unroll: 4 independent LDG.64 in flight,
// separate accumulators per view parity.
// ---------------------------------------------------------------------------
__global__ __launch_bounds__(256, 4) void bp_kernel(float* __restrict__ out) {
    __shared__ __align__(16) float4 strig[V];

    const int tid = threadIdx.y * 32 + threadIdx.x;
    {
        const float4* src = g_trig;
        for (int i = tid; i < V; i += 256) strig[i] = src[i];
    }
    __syncthreads();

    const int iy  = blockIdx.x * 32 + threadIdx.x;
    const int ix0 = blockIdx.y * 16 + threadIdx.y;   // second pixel: ix0 + 8

    const float dx   = (float)(SVOX_D / (double)NXY);
    const float y    = ((float)iy  - 255.5f) * dx;
    const float x0   = ((float)ix0 - 255.5f) * dx;
    const float stp  = 8.0f * dx;
    const float c0   = 367.5f;
    const float dso  = (float)DSO_D;
    const float uMax = (float)(U - 1);

    float accA0 = 0.0f, accA1 = 0.0f, accB0 = 0.0f, accB1 = 0.0f;

    #pragma unroll 2
    for (int v = 0; v < V; v += 2) {
        float4 ta = strig[v];
        float4 tb = strig[v + 1];

        // geometry for both views, both pixels
        float tA0 = fmaf(x0, ta.x, y * ta.y);
        float tA1 = fmaf(stp, ta.x, tA0);
        float DA0 = fmaf(x0, ta.w, fmaf(-y, ta.z, dso));
        float DA1 = fmaf(stp, ta.w, DA0);
        float tB0 = fmaf(x0, tb.x, y * tb.y);
        float tB1 = fmaf(stp, tb.x, tB0);
        float DB0 = fmaf(x0, tb.w, fmaf(-y, tb.z, dso));
        float DB1 = fmaf(stp, tb.w, DB0);

        float rA0, rA1, rB0, rB1;
        asm("rcp.approx.f32 %0, %1;" : "=f"(rA0) : "f"(DA0));
        asm("rcp.approx.f32 %0, %1;" : "=f"(rA1) : "f"(DA1));
        asm("rcp.approx.f32 %0, %1;" : "=f"(rB0) : "f"(DB0));
        asm("rcp.approx.f32 %0, %1;" : "=f"(rB1) : "f"(DB1));

        float iA0 = fmaf(tA0, rA0, c0);
        float iA1 = fmaf(tA1, rA1, c0);
        float iB0 = fmaf(tB0, rB0, c0);
        float iB1 = fmaf(tB1, rB1, c0);

        int jA0 = max(0, min(U - 2, __float2int_rd(iA0)));
        int jA1 = max(0, min(U - 2, __float2int_rd(iA1)));
        int jB0 = max(0, min(U - 2, __float2int_rd(iB0)));
        int jB1 = max(0, min(U - 2, __float2int_rd(iB1)));

        // all 4 loads in flight before any consumption
        const float2* qa = g_Qp + v * U;
        const float2* qb = g_Qp + (v + 1) * U;
        float2 qA0 = __ldg(qa + jA0);
        float2 qA1 = __ldg(qa + jA1);
        float2 qB0 = __ldg(qb + jB0);
        float2 qB1 = __ldg(qb + jB1);

        float fA0 = iA0 - (float)jA0;
        float fA1 = iA1 - (float)jA1;
        float fB0 = iB0 - (float)jB0;
        float fB1 = iB1 - (float)jB1;

        float vA0 = fmaf(fA0, qA0.y - qA0.x, qA0.x);
        float vA1 = fmaf(fA1, qA1.y - qA1.x, qA1.x);
        float vB0 = fmaf(fB0, qB0.y - qB0.x, qB0.x);
        float vB1 = fmaf(fB1, qB1.y - qB1.x, qB1.x);

        vA0 = ((iA0 >= 0.0f) && (iA0 <= uMax)) ? vA0 : 0.0f;
        vA1 = ((iA1 >= 0.0f) && (iA1 <= uMax)) ? vA1 : 0.0f;
        vB0 = ((iB0 >= 0.0f) && (iB0 <= uMax)) ? vB0 : 0.0f;
        vB1 = ((iB1 >= 0.0f) && (iB1 <= uMax)) ? vB1 : 0.0f;

        accA0 = fmaf(vA0, rA0 * rA0, accA0);
        accA1 = fmaf(vA1, rA1 * rA1, accA1);
        accB0 = fmaf(vB0, rB0 * rB0, accB0);
        accB1 = fmaf(vB1, rB1 * rB1, accB1);
    }

    const float scale = (float)(0.5 * (2.0 * PI_D / (double)V) * DSO_D * DSO_D);
    out[ix0 * NXY + iy]       = (accA0 + accB0) * scale;
    out[(ix0 + 8) * NXY + iy] = (accA1 + accB1) * scale;
}

// ---------------------------------------------------------------------------
extern "C" void kernel_launch(void* const* d_in, const int* in_sizes, int n_in,
                              void* d_out, int out_size) {
    (void)in_sizes; (void)n_in; (void)out_size;
    const float* sino = (const float*)d_in[0];
    float* out = (float*)d_out;

    filter_kernel<<<V, 192>>>(sino);
    dim3 bpBlock(32, 8);
    dim3 bpGrid(NXY / 32, NXY / 16);   // 16 x 32 = 512 blocks
    bp_kernel<<<bpGrid, bpBlock>>>(out);
}

// round 7
// speedup vs baseline: 2.1380x; 1.2112x over previous
#include <cuda_runtime.h>
#include <math.h>

#define V 720
#define U 736
#define NXY 512
#define NTAPS 368

#define DU_D   1.2858
#define DSO_D  595.0
#define DOD_D  490.6
#define DSD_D  (DSO_D + DOD_D)
#define SVOX_D 400.0
#define PI_D   3.14159265358979323846

// parity-packed conv arrays
#define PADE 380
#define PODD 383
#define WLEN 1124

// guard-band padded filtered rows: slot i holds detector index u = i - QPAD
#define QPAD 512
#define QSTRIDE 1760            // 512 + 736 + 512

// ---- device-global scratch ----
__device__ float4 g_trig[V];          // (cb*DSD/DU, sb*DSD/DU, cb, sb)
__device__ float2 g_Qp[V * QSTRIDE];  // (Q[u], Q[u+1]-Q[u]); (0,0) outside [0,U-2]

// ---------------------------------------------------------------------------
// Kernel 1: cosine weight + Ram-Lak conv (parity-packed, register-tiled),
// one block (192 thr) per view. Writes trig table + padded (q, dq) rows.
// ---------------------------------------------------------------------------
__global__ __launch_bounds__(192) void filter_kernel(const float* __restrict__ sino) {
    __shared__ __align__(16) float wo_s[WLEN];
    __shared__ __align__(16) float we_s[WLEN];
    __shared__ __align__(16) float ho_s[NTAPS];
    __shared__ float qrow[U];

    const int v = blockIdx.x;
    const int tid = threadIdx.x;

    for (int i = tid; i < WLEN; i += 192) { wo_s[i] = 0.0f; we_s[i] = 0.0f; }
    for (int k = tid; k < NTAPS; k += 192) {
        float d = (float)(PI_D * DU_D) * (float)(2 * k + 1);
        ho_s[k] = -1.0f / (d * d);
    }
    if (tid == 0) {
        float bf = (float)(2.0 * PI_D * (double)v / (double)V);
        float cb = (float)cos((double)bf);
        float sb = (float)sin((double)bf);
        float kk = (float)(DSD_D / DU_D);
        g_trig[v] = make_float4(cb * kk, sb * kk, cb, sb);
    }
    __syncthreads();

    {
        const float* row = sino + v * U;
        const float dsd  = (float)DSD_D;
        const float dsd2 = (float)(DSD_D * DSD_D);
        const float du   = (float)DU_D;
        for (int u = tid; u < U; u += 192) {
            float us = ((float)u - 367.5f) * du;
            float w = row[u] * (dsd * rsqrtf(dsd2 + us * us));
            if (u & 1) wo_s[PADE + (u >> 1)] = w;
            else       we_s[PODD + (u >> 1)] = w;
        }
    }
    __syncthreads();

    const int grp = tid / 96;
    const int t   = tid % 96;
    if (t < 92) {
        const int b = 4 * t;
        const float* A = grp ? (we_s + PODD + 1) : (wo_s + PADE);
        const float* C = grp ? (wo_s + PADE)     : (we_s + PODD);
        const float h0 = (float)(1.0 / (4.0 * DU_D * DU_D));

        float acc0 = h0 * C[b + 0];
        float acc1 = h0 * C[b + 1];
        float acc2 = h0 * C[b + 2];
        float acc3 = h0 * C[b + 3];

        float4 Llo = *(const float4*)(A + b - 4);
        float4 Lhi = *(const float4*)(A + b);
        float4 rlo = *(const float4*)(A + b);
        float4 rhi = *(const float4*)(A + b + 4);

        #pragma unroll 4
        for (int j = 0; j < 92; j++) {
            float4 h4 = *(const float4*)(ho_s + 4 * j);
            acc0 += h4.x * (Llo.w + rlo.x);
            acc1 += h4.x * (Lhi.x + rlo.y);
            acc2 += h4.x * (Lhi.y + rlo.z);
            acc3 += h4.x * (Lhi.z + rlo.w);
            acc0 += h4.y * (Llo.z + rlo.y);
            acc1 += h4.y * (Llo.w + rlo.z);
            acc2 += h4.y * (Lhi.x + rlo.w);
            acc3 += h4.y * (Lhi.y + rhi.x);
            acc0 += h4.z * (Llo.y + rlo.z);
            acc1 += h4.z * (Llo.z + rlo.w);
            acc2 += h4.z * (Llo.w + rhi.x);
            acc3 += h4.z * (Lhi.x + rhi.y);
            acc0 += h4.w * (Llo.x + rlo.w);
            acc1 += h4.w * (Llo.y + rhi.x);
            acc2 += h4.w * (Llo.z + rhi.y);
            acc3 += h4.w * (Llo.w + rhi.z);
            Lhi = Llo;
            Llo = *(const float4*)(A + b - 4 * j - 8);
            rlo = rhi;
            rhi = *(const float4*)(A + b + 4 * j + 8);
        }

        const float du = (float)DU_D;
        const int u0 = 8 * t + grp;
        qrow[u0 + 0] = du * acc0;
        qrow[u0 + 2] = du * acc1;
        qrow[u0 + 4] = du * acc2;
        qrow[u0 + 6] = du * acc3;
    }
    __syncthreads();

    // padded (q, dq) pairs: slot i <-> u = i - QPAD.
    // EXACT reference masking: any slot outside [0, U-2] is (0,0) so the lerp
    // returns 0 exactly where the reference zeroes (idx<0 or idx>U-1).
    {
        float2* dst = g_Qp + v * QSTRIDE;
        for (int i = tid; i < QSTRIDE; i += 192) {
            int s = i - QPAD;
            bool in = (s >= 0) && (s <= U - 2);
            float q0 = in ? qrow[s] : 0.0f;
            float q1 = in ? qrow[s + 1] : 0.0f;
            dst[i] = make_float2(q0, q1 - q0);
        }
    }
}

// ---------------------------------------------------------------------------
// Kernel 2: weighted fan-beam backprojection.
// Block (32,8): iy = bx*32+tx, pixels ix0 = by*16+ty and ix0+8.
// 2-view x 2-pixel unroll; guard-banded Q -> no clamps, no bounds predicates.
// ---------------------------------------------------------------------------
__global__ __launch_bounds__(256, 4) void bp_kernel(float* __restrict__ out) {
    __shared__ __align__(16) float4 strig[V];

    const int tid = threadIdx.y * 32 + threadIdx.x;
    for (int i = tid; i < V; i += 256) strig[i] = g_trig[i];
    __syncthreads();

    const int iy  = blockIdx.x * 32 + threadIdx.x;
    const int ix0 = blockIdx.y * 16 + threadIdx.y;   // second pixel: ix0 + 8

    const float dx   = (float)(SVOX_D / (double)NXY);
    const float y    = ((float)iy  - 255.5f) * dx;
    const float x0   = ((float)ix0 - 255.5f) * dx;
    const float stp  = 8.0f * dx;
    const float c0   = 367.5f + (float)QPAD;         // integer guard shift folded in
    const float dso  = (float)DSO_D;

    float accA0 = 0.0f, accA1 = 0.0f, accB0 = 0.0f, accB1 = 0.0f;

    #pragma unroll 2
    for (int v = 0; v < V; v += 2) {
        float4 ta = strig[v];
        float4 tb = strig[v + 1];

        float tA0 = fmaf(x0, ta.x, y * ta.y);
        float tA1 = fmaf(stp, ta.x, tA0);
        float DA0 = fmaf(x0, ta.w, fmaf(-y, ta.z, dso));
        float DA1 = fmaf(stp, ta.w, DA0);
        float tB0 = fmaf(x0, tb.x, y * tb.y);
        float tB1 = fmaf(stp, tb.x, tB0);
        float DB0 = fmaf(x0, tb.w, fmaf(-y, tb.z, dso));
        float DB1 = fmaf(stp, tb.w, DB0);

        float rA0, rA1, rB0, rB1;
        asm("rcp.approx.f32 %0, %1;" : "=f"(rA0) : "f"(DA0));
        asm("rcp.approx.f32 %0, %1;" : "=f"(rA1) : "f"(DA1));
        asm("rcp.approx.f32 %0, %1;" : "=f"(rB0) : "f"(DB0));
        asm("rcp.approx.f32 %0, %1;" : "=f"(rB1) : "f"(DB1));

        float iA0 = fmaf(tA0, rA0, c0);
        float iA1 = fmaf(tA1, rA1, c0);
        float iB0 = fmaf(tB0, rB0, c0);
        float iB1 = fmaf(tB1, rB1, c0);

        // always positive & in-bounds (guard bands) -> truncation == floor
        int jA0 = __float2int_rz(iA0);
        int jA1 = __float2int_rz(iA1);
        int jB0 = __float2int_rz(iB0);
        int jB1 = __float2int_rz(iB1);

        const float2* qa = g_Qp + v * QSTRIDE;
        const float2* qb = g_Qp + (v + 1) * QSTRIDE;
        float2 qA0 = __ldg(qa + jA0);
        float2 qA1 = __ldg(qa + jA1);
        float2 qB0 = __ldg(qb + jB0);
        float2 qB1 = __ldg(qb + jB1);

        float fA0 = iA0 - (float)jA0;
        float fA1 = iA1 - (float)jA1;
        float fB0 = iB0 - (float)jB0;
        float fB1 = iB1 - (float)jB1;

        float vA0 = fmaf(fA0, qA0.y, qA0.x);
        float vA1 = fmaf(fA1, qA1.y, qA1.x);
        float vB0 = fmaf(fB0, qB0.y, qB0.x);
        float vB1 = fmaf(fB1, qB1.y, qB1.x);

        accA0 = fmaf(vA0, rA0 * rA0, accA0);
        accA1 = fmaf(vA1, rA1 * rA1, accA1);
        accB0 = fmaf(vB0, rB0 * rB0, accB0);
        accB1 = fmaf(vB1, rB1 * rB1, accB1);
    }

    const float scale = (float)(0.5 * (2.0 * PI_D / (double)V) * DSO_D * DSO_D);
    out[ix0 * NXY + iy]       = (accA0 + accB0) * scale;
    out[(ix0 + 8) * NXY + iy] = (accA1 + accB1) * scale;
}

// ---------------------------------------------------------------------------
extern "C" void kernel_launch(void* const* d_in, const int* in_sizes, int n_in,
                              void* d_out, int out_size) {
    (void)in_sizes; (void)n_in; (void)out_size;
    const float* sino = (const float*)d_in[0];
    float* out = (float*)d_out;

    filter_kernel<<<V, 192>>>(sino);
    dim3 bpBlock(32, 8);
    dim3 bpGrid(NXY / 32, NXY / 16);   // 16 x 32 = 512 blocks
    bp_kernel<<<bpGrid, bpBlock>>>(out);
}